// round 8
// baseline (speedup 1.0000x reference)
#include <cuda_runtime.h>
#include <cuda_fp16.h>
#include <math.h>
#include <stdint.h>

#define BSZ   32
#define LQ    512
#define DM    768
#define NHID  192
#define KC    5
#define DI    1536
#define DS    16
#define DTR   48
#define DXP   (DTR+2*DS)      // 112
#define DCONV 4
#define ML    (BSZ*LQ)        // 16384 rows
#define EPSV  1e-5f
#define BNCH  32              // BN stats row-chunks

// fp16-mma GEMM tiling: CTA 128x128, K-chunk 32 halfs, 8 warps 4x2
#define TGK     32
#define PITCHW  20
#define TILEW   (128*PITCHW)
#define TG_SMEMB (4*TILEW*4)            // 40960 bytes

// weight scratch offsets (halfs)
#define OFF_SQ  0
#define OFF_EX  147456
#define OFF_INP 294912
#define OFF_XP  2654208
#define OFF_DT  2826240
#define OFF_OP  2899968
#define OFF_GW  4079616
#define WH_TOT  4669440

// ---------------- scratch buffers ----------------
__device__ __half g_wh [WH_TOT];
__device__ __half g_h  [ML*NHID];
__device__ __half g_h2 [ML*NHID];
__device__ __half g_xnh[ML*DM];
__device__ __half g_xm [(size_t)ML*DI];
__device__ __half g_z  [(size_t)ML*DI];
__device__ __half g_xmc[(size_t)ML*DI];
__device__ __half g_dbc[ML*DXP];
__device__ __half g_del[(size_t)ML*DI];
__device__ __half g_y  [(size_t)ML*DI];
__device__ __half g_mo [ML*DM];
__device__ __half g_gt [ML*DM];
__device__ float  g_x1 [ML*DM];
__device__ float  g_xf [ML*DM];
__device__ float  g_rm [ML];
__device__ float  g_rs [ML];
__device__ float  g_cm [4096];
__device__ float  g_cs [4096];
__device__ float  g_ps [BNCH*1024];
__device__ float  g_pq [BNCH*1024];

// ===================== helpers =============================================
__device__ __forceinline__ void mma_f16(float* d, const uint32_t* a, const uint32_t* b) {
    asm volatile(
        "mma.sync.aligned.m16n8k16.row.col.f32.f16.f16.f32 "
        "{%0,%1,%2,%3}, {%4,%5,%6,%7}, {%8,%9}, {%0,%1,%2,%3};"
        : "+f"(d[0]), "+f"(d[1]), "+f"(d[2]), "+f"(d[3])
        : "r"(a[0]), "r"(a[1]), "r"(a[2]), "r"(a[3]), "r"(b[0]), "r"(b[1]));
}
__device__ __forceinline__ float fsilu(float v)   { return __fdividef(v, 1.f + __expf(-v)); }
__device__ __forceinline__ float fsigm(float v)   { return __fdividef(1.f, 1.f + __expf(-v)); }

// ---------------- converts -------------------------------------------------
__global__ void f2h2(const float* __restrict__ src, __half* __restrict__ dst, long n)
{
    long i = ((long)blockIdx.x * blockDim.x + threadIdx.x) * 2;
    if (i >= n) return;
    float2 v = *(const float2*)(src + i);
    *(__half2*)(dst + i) = __floats2half2_rn(v.x, v.y);
}
__global__ void wconv(const float* __restrict__ s0, const float* __restrict__ s1,
                      const float* __restrict__ s2, const float* __restrict__ s3,
                      const float* __restrict__ s4, const float* __restrict__ s5,
                      const float* __restrict__ s6, __half* __restrict__ dst)
{
    long i = ((long)blockIdx.x * blockDim.x + threadIdx.x) * 2;
    if (i >= WH_TOT) return;
    const float* src; long off;
    if      (i < OFF_EX)  { src = s0; off = i - OFF_SQ;  }
    else if (i < OFF_INP) { src = s1; off = i - OFF_EX;  }
    else if (i < OFF_XP)  { src = s2; off = i - OFF_INP; }
    else if (i < OFF_DT)  { src = s3; off = i - OFF_XP;  }
    else if (i < OFF_OP)  { src = s4; off = i - OFF_DT;  }
    else if (i < OFF_GW)  { src = s5; off = i - OFF_OP;  }
    else                  { src = s6; off = i - OFF_GW;  }
    float2 v = *(const float2*)(src + off);
    *(__half2*)(dst + i) = __floats2half2_rn(v.x, v.y);
}

// ===================== fp16 tensor GEMM ====================================
__global__ void __launch_bounds__(256, 2)
tgemm(const __half* __restrict__ A, int lda,
      const __half* __restrict__ W, int ldw,
      const float* __restrict__ bias,
      __half* __restrict__ C, int ldc,
      __half* __restrict__ C2, int ldc2, int splitN,
      int M, int N, int K, int act)
{
    extern __shared__ uint32_t smem[];
    const int tid = threadIdx.x;
    const int wid = tid >> 5, lane = tid & 31;
    const int g = lane >> 2, t = lane & 3;
    const int wm = wid & 3, wn = wid >> 2;
    const int row0 = blockIdx.y * 128, col0 = blockIdx.x * 128;

    float acc[2][8][4];
#pragma unroll
    for (int mt = 0; mt < 2; mt++)
#pragma unroll
        for (int nt = 0; nt < 8; nt++)
#pragma unroll
            for (int j = 0; j < 4; j++) acc[mt][nt][j] = 0.f;

    const int nch = (K + TGK - 1) / TGK;

    uint4 pa[2], pb[2];
    auto ldg_chunk = [&](int ch) {
        const int k0 = ch * TGK;
#pragma unroll
        for (int i = 0; i < 2; i++) {
            int e = tid + i * 256;
            int r = e >> 2, q = e & 3;
            int gk = k0 + q * 8;
            pa[i] = make_uint4(0, 0, 0, 0);
            pb[i] = make_uint4(0, 0, 0, 0);
            if (gk < K) {
                pa[i] = *(const uint4*)(A + (long)(row0 + r) * lda + gk);
                int n = col0 + r;
                if (n < N) pb[i] = *(const uint4*)(W + (long)n * ldw + gk);
            }
        }
    };
    auto sts_chunk = [&](int buf) {
        uint32_t* As = smem + buf * 2 * TILEW;
        uint32_t* Bs = As + TILEW;
#pragma unroll
        for (int i = 0; i < 2; i++) {
            int e = tid + i * 256;
            int r = e >> 2, q = e & 3;
            int o = r * PITCHW + q * 4;
            *(uint4*)(As + o) = pa[i];
            *(uint4*)(Bs + o) = pb[i];
        }
    };
    auto compute_chunk = [&](int buf) {
        const uint32_t* As = smem + buf * 2 * TILEW;
        const uint32_t* Bs = As + TILEW;
#pragma unroll
        for (int ks = 0; ks < 2; ks++) {
            const int kw = ks * 8;
            uint32_t af[2][4], bf[8][2];
#pragma unroll
            for (int mt = 0; mt < 2; mt++) {
                int ar = wm * 32 + mt * 16;
                af[mt][0] = As[(ar + g)     * PITCHW + kw + t];
                af[mt][1] = As[(ar + g + 8) * PITCHW + kw + t];
                af[mt][2] = As[(ar + g)     * PITCHW + kw + t + 4];
                af[mt][3] = As[(ar + g + 8) * PITCHW + kw + t + 4];
            }
#pragma unroll
            for (int nt = 0; nt < 8; nt++) {
                int br = wn * 64 + nt * 8;
                bf[nt][0] = Bs[(br + g) * PITCHW + kw + t];
                bf[nt][1] = Bs[(br + g) * PITCHW + kw + t + 4];
            }
#pragma unroll
            for (int mt = 0; mt < 2; mt++)
#pragma unroll
                for (int nt = 0; nt < 8; nt++)
                    mma_f16(acc[mt][nt], af[mt], bf[nt]);
        }
    };

    ldg_chunk(0);
    sts_chunk(0);
    __syncthreads();
    for (int ch = 1; ch < nch; ch++) {
        ldg_chunk(ch);
        compute_chunk((ch - 1) & 1);
        sts_chunk(ch & 1);
        __syncthreads();
    }
    compute_chunk((nch - 1) & 1);

    __half* Cp = C; int cof = col0, ldco = ldc;
    if (C2 && col0 >= splitN) { Cp = C2; cof = col0 - splitN; ldco = ldc2; }
#pragma unroll
    for (int mt = 0; mt < 2; mt++) {
        int r0 = row0 + wm * 32 + mt * 16 + g;
#pragma unroll
        for (int nt = 0; nt < 8; nt++) {
            int c0 = cof + wn * 64 + nt * 8 + t * 2;
            int cg = col0 + wn * 64 + nt * 8 + t * 2;
            if (cg >= N) continue;
#pragma unroll
            for (int half_ = 0; half_ < 2; half_++) {
                int r = r0 + half_ * 8;
                float v0 = acc[mt][nt][half_ * 2 + 0];
                float v1 = acc[mt][nt][half_ * 2 + 1];
                if (bias) { v0 += bias[cg]; v1 += bias[cg + 1]; }
                if (act == 2) {
                    v0 = (v0 > 20.f) ? v0 : log1pf(__expf(v0));
                    v1 = (v1 > 20.f) ? v1 : log1pf(__expf(v1));
                } else if (act == 3) {
                    v0 = fsigm(v0);
                    v1 = fsigm(v1);
                }
                *(__half2*)(Cp + (long)r * ldco + c0) = __floats2half2_rn(v0, v1);
            }
        }
    }
}

// ===================== two-phase BN stats ==================================
__global__ void bn_part(const __half* __restrict__ src, int M, int N,
                        float* __restrict__ ps, float* __restrict__ pq)
{
    int c = blockIdx.x * 32 + threadIdx.x;
    int ch = blockIdx.y;
    int rows = M / BNCH;
    int r0 = ch * rows;
    float s = 0.f, sq = 0.f;
    if (c < N) {
        for (int r = r0 + threadIdx.y; r < r0 + rows; r += blockDim.y) {
            float v = __half2float(src[(long)r * N + c]);
            s += v; sq += v * v;
        }
    }
    __shared__ float sh[32][33], sh2[32][33];
    sh[threadIdx.y][threadIdx.x] = s;
    sh2[threadIdx.y][threadIdx.x] = sq;
    __syncthreads();
    if (threadIdx.y == 0 && c < N) {
#pragma unroll
        for (int i = 1; i < 32; i++) { s += sh[i][threadIdx.x]; sq += sh2[i][threadIdx.x]; }
        ps[ch * N + c] = s;
        pq[ch * N + c] = sq;
    }
}
__global__ void bn_final(const float* __restrict__ ps, const float* __restrict__ pq,
                         int M, int N, float* __restrict__ mean, float* __restrict__ rstd)
{
    int c = blockIdx.x * blockDim.x + threadIdx.x;
    if (c >= N) return;
    float s = 0.f, sq = 0.f;
#pragma unroll
    for (int ch = 0; ch < BNCH; ch++) { s += ps[ch * N + c]; sq += pq[ch * N + c]; }
    float m = s / (float)M;
    mean[c] = m;
    rstd[c] = rsqrtf(fmaxf(sq / (float)M - m * m, 0.f) + EPSV);
}

// BN apply half->half (+silu)
__global__ void bn_apply_hh(const __half* __restrict__ src, __half* __restrict__ dst,
                            const float* __restrict__ mean, const float* __restrict__ rstd,
                            const float* __restrict__ g, const float* __restrict__ b,
                            long total, int N)
{
    long i = (long)blockIdx.x * blockDim.x + threadIdx.x;
    if (i >= total) return;
    int c = (int)(i % N);
    float v = (__half2float(src[i]) - mean[c]) * rstd[c] * g[c] + b[c];
    dst[i] = __float2half_rn(fsilu(v));
}

__global__ void dwconv5_h(const __half* __restrict__ src, const float* __restrict__ w,
                          __half* __restrict__ dst)
{
    long i = (long)blockIdx.x * blockDim.x + threadIdx.x;
    if (i >= (long)ML * NHID) return;
    int c = (int)(i % NHID);
    long bl = i / NHID;
    int l = (int)(bl % LQ);
    long b = bl / LQ;
    float acc = 0.f;
#pragma unroll
    for (int k = 0; k < KC; k++) {
        int ll = l + k - 2;
        if (ll >= 0 && ll < LQ)
            acc += __half2float(src[(b * LQ + ll) * NHID + c]) * w[c * KC + k];
    }
    dst[i] = __float2half_rn(acc);
}

__global__ void cconv4_h(const __half* __restrict__ xm, const float* __restrict__ w,
                         const float* __restrict__ cb, __half* __restrict__ dst)
{
    long i = (long)blockIdx.x * blockDim.x + threadIdx.x;
    if (i >= (long)ML * DI) return;
    int c = (int)(i % DI);
    long bl = i / DI;
    int l = (int)(bl % LQ);
    long b = bl / LQ;
    float acc = cb[c];
#pragma unroll
    for (int k = 0; k < DCONV; k++) {
        int ll = l + k - (DCONV - 1);
        if (ll >= 0)
            acc += __half2float(xm[(b * LQ + ll) * (long)DI + c]) * w[c * DCONV + k];
    }
    dst[i] = __float2half_rn(fsilu(acc));
}

// fused BN(ex)+residual -> x1 ; LN stats ; LN apply -> xn (half)
__global__ void bnx1_ln(const __half* __restrict__ mo, const float* __restrict__ x,
                        const float* __restrict__ cm, const float* __restrict__ cs,
                        const float* __restrict__ exg, const float* __restrict__ exb,
                        const float* __restrict__ mg, const float* __restrict__ mb,
                        float* __restrict__ x1, __half* __restrict__ xn,
                        float* __restrict__ rm, float* __restrict__ rs)
{
    int r = blockIdx.x;
    long base = (long)r * DM;
    float v[3];
#pragma unroll
    for (int i = 0; i < 3; i++) {
        int c = threadIdx.x + i * 256;
        float bn = (__half2float(mo[base + c]) - cm[c]) * cs[c] * exg[c] + exb[c];
        v[i] = bn + x[base + c];
        x1[base + c] = v[i];
    }
    float s = v[0] + v[1] + v[2];
    float sq = v[0] * v[0] + v[1] * v[1] + v[2] * v[2];
    __shared__ float sh[256], sh2[256];
    sh[threadIdx.x] = s; sh2[threadIdx.x] = sq;
    __syncthreads();
    for (int st = 128; st > 0; st >>= 1) {
        if (threadIdx.x < st) { sh[threadIdx.x] += sh[threadIdx.x + st]; sh2[threadIdx.x] += sh2[threadIdx.x + st]; }
        __syncthreads();
    }
    float m = sh[0] / (float)DM;
    float rstd = rsqrtf(fmaxf(sh2[0] / (float)DM - m * m, 0.f) + EPSV);
    if (threadIdx.x == 0) { rm[r] = m; rs[r] = rstd; }
#pragma unroll
    for (int i = 0; i < 3; i++) {
        int c = threadIdx.x + i * 256;
        xn[base + c] = __float2half_rn((v[i] - m) * rstd * mg[c] + mb[c]);
    }
}

// fused x_final + LN stats
__global__ void xfinal_ln(const float* __restrict__ x1, const __half* __restrict__ mo,
                          const __half* __restrict__ gt, const float* __restrict__ x,
                          float* __restrict__ xf, float* __restrict__ rm,
                          float* __restrict__ rs)
{
    int r = blockIdx.x;
    long base = (long)r * DM;
    float v[3];
#pragma unroll
    for (int i = 0; i < 3; i++) {
        int c = threadIdx.x + i * 256;
        v[i] = x1[base + c] + __half2float(mo[base + c]) * __half2float(gt[base + c]) + x[base + c];
        xf[base + c] = v[i];
    }
    float s = v[0] + v[1] + v[2];
    float sq = v[0] * v[0] + v[1] * v[1] + v[2] * v[2];
    __shared__ float sh[256], sh2[256];
    sh[threadIdx.x] = s; sh2[threadIdx.x] = sq;
    __syncthreads();
    for (int st = 128; st > 0; st >>= 1) {
        if (threadIdx.x < st) { sh[threadIdx.x] += sh[threadIdx.x + st]; sh2[threadIdx.x] += sh2[threadIdx.x + st]; }
        __syncthreads();
    }
    if (threadIdx.x == 0) {
        float m = sh[0] / (float)DM;
        rm[r] = m;
        rs[r] = rsqrtf(fmaxf(sh2[0] / (float)DM - m * m, 0.f) + EPSV);
    }
}

// feat_attr: max over L of LN(x1)*g+b ; block (32 d, 8 lgroup), grid (DM/32, BSZ)
__global__ void feat_attr_k(const float* __restrict__ x1, const float* __restrict__ rm,
                            const float* __restrict__ rs, const float* __restrict__ g,
                            const float* __restrict__ b, float* __restrict__ out)
{
    int d = blockIdx.x * 32 + threadIdx.x;
    int bb = blockIdx.y;
    float gd = g[d], bd = b[d];
    float best = -1e30f;
    for (int l = threadIdx.y; l < LQ; l += 8) {
        long row = (long)bb * LQ + l;
        float v = (x1[row * DM + d] - rm[row]) * rs[row] * gd + bd;
        best = fmaxf(best, v);
    }
    __shared__ float sh[8][33];
    sh[threadIdx.y][threadIdx.x] = best;
    __syncthreads();
    if (threadIdx.y == 0) {
#pragma unroll
        for (int i = 1; i < 8; i++) best = fmaxf(best, sh[i][threadIdx.x]);
        out[(long)bb * DM + d] = best;
    }
}

// feat_id: mean over L of LN(xf); same layout
__global__ void feat_id_k(const float* __restrict__ xf, const float* __restrict__ rm,
                          const float* __restrict__ rs, const float* __restrict__ g,
                          const float* __restrict__ b, float* __restrict__ out)
{
    int d = blockIdx.x * 32 + threadIdx.x;
    int bb = blockIdx.y;
    float acc = 0.f;
    for (int l = threadIdx.y; l < LQ; l += 8) {
        long row = (long)bb * LQ + l;
        acc += (xf[row * DM + d] - rm[row]) * rs[row];
    }
    __shared__ float sh[8][33];
    sh[threadIdx.y][threadIdx.x] = acc;
    __syncthreads();
    if (threadIdx.y == 0) {
#pragma unroll
        for (int i = 1; i < 8; i++) acc += sh[i][threadIdx.x];
        out[(long)bb * DM + d] = (acc / (float)LQ) * g[d] + b[d];
    }
}

__global__ void idbn_k(const float* __restrict__ fid, const float* __restrict__ g,
                       const float* __restrict__ b, float* __restrict__ out)
{
    int d = blockIdx.x * blockDim.x + threadIdx.x;
    if (d >= DM) return;
    float s = 0.f;
    for (int bb = 0; bb < BSZ; bb++) s += fid[(long)bb * DM + d];
    float m = s / (float)BSZ;
    float vq = 0.f;
    for (int bb = 0; bb < BSZ; bb++) { float dv = fid[(long)bb * DM + d] - m; vq += dv * dv; }
    float rst = rsqrtf(vq / (float)BSZ + EPSV);
    for (int bb = 0; bb < BSZ; bb++)
        out[(long)bb * DM + d] = (fid[(long)bb * DM + d] - m) * rst * g[d] + b[d];
}

// ---------------- selective scan (half inputs, prefetched) ----------------
__global__ void __launch_bounds__(128)
scan_k(const __half* __restrict__ xmc, const __half* __restrict__ del,
       const __half* __restrict__ dbc, const __half* __restrict__ z,
       const float* __restrict__ A_log, const float* __restrict__ Dp,
       __half* __restrict__ y)
{
    int b = blockIdx.y;
    int d = blockIdx.x * 128 + threadIdx.x;
    float A[DS], h[DS];
    bool fast = true;
#pragma unroll
    for (int s = 0; s < DS; s++) {
        A[s] = -expf(A_log[(long)d * DS + s]);
        h[s] = 0.f;
        fast = fast && (fabsf(A[s] + (float)(s + 1)) < 1e-4f * (float)(s + 1));
    }
    float Dpv = Dp[d];
    const long rb0 = (long)b * LQ;
    const __half* dbcb = dbc + rb0 * DXP + DTR;

    float dv = __half2float(del[rb0 * DI + d]);
    float uv = __half2float(xmc[rb0 * DI + d]);
    float zv = __half2float(z[rb0 * DI + d]);
    uint4 bc[4];
#pragma unroll
    for (int i = 0; i < 4; i++) bc[i] = *(const uint4*)(dbcb + i * 8);

    for (int l = 0; l < LQ; l++) {
        float dvn = 0.f, uvn = 0.f, zvn = 0.f;
        uint4 bcn[4] = {};
        if (l + 1 < LQ) {
            long rb = rb0 + l + 1;
            dvn = __half2float(del[rb * DI + d]);
            uvn = __half2float(xmc[rb * DI + d]);
            zvn = __half2float(z[rb * DI + d]);
            const __half* p = dbcb + (long)(l + 1) * DXP;
#pragma unroll
            for (int i = 0; i < 4; i++) bcn[i] = *(const uint4*)(p + i * 8);
        }

        float Bv[DS], Cv[DS];
#pragma unroll
        for (int i = 0; i < 2; i++) {
            const __half2* hb = (const __half2*)&bc[i];
#pragma unroll
            for (int j = 0; j < 4; j++) {
                float2 f = __half22float2(hb[j]);
                Bv[i * 8 + j * 2] = f.x; Bv[i * 8 + j * 2 + 1] = f.y;
            }
            const __half2* hc = (const __half2*)&bc[i + 2];
#pragma unroll
            for (int j = 0; j < 4; j++) {
                float2 f = __half22float2(hc[j]);
                Cv[i * 8 + j * 2] = f.x; Cv[i * 8 + j * 2 + 1] = f.y;
            }
        }

        float du = dv * uv;
        float yv = 0.f;
        if (fast) {
            float p = __expf(-dv), e = 1.f;
#pragma unroll
            for (int s = 0; s < DS; s++) {
                e *= p;
                h[s] = h[s] * e + du * Bv[s];
                yv += h[s] * Cv[s];
            }
        } else {
#pragma unroll
            for (int s = 0; s < DS; s++) {
                float e = __expf(dv * A[s]);
                h[s] = h[s] * e + du * Bv[s];
                yv += h[s] * Cv[s];
            }
        }
        yv += uv * Dpv;
        y[(rb0 + l) * DI + d] = __float2half_rn(yv * fsilu(zv));

        dv = dvn; uv = uvn; zv = zvn;
#pragma unroll
        for (int i = 0; i < 4; i++) bc[i] = bcn[i];
    }
}

// ======================== host launcher ====================================
static inline dim3 tg_grid(int N) { return dim3((N + 127) / 128, ML / 128); }

extern "C" void kernel_launch(void* const* d_in, const int* in_sizes, int n_in,
                              void* d_out, int out_size)
{
    (void)in_sizes; (void)n_in; (void)out_size;
    const float* x         = (const float*)d_in[0];
    const float* sq_w      = (const float*)d_in[1];
    const float* sq_bn_g   = (const float*)d_in[2];
    const float* sq_bn_b   = (const float*)d_in[3];
    const float* dw_w      = (const float*)d_in[4];
    const float* dw_bn_g   = (const float*)d_in[5];
    const float* dw_bn_b   = (const float*)d_in[6];
    const float* ex_w      = (const float*)d_in[7];
    const float* ex_bn_g   = (const float*)d_in[8];
    const float* ex_bn_b   = (const float*)d_in[9];
    const float* attr_g    = (const float*)d_in[10];
    const float* attr_b    = (const float*)d_in[11];
    const float* mnorm_g   = (const float*)d_in[12];
    const float* mnorm_b   = (const float*)d_in[13];
    const float* in_proj_w = (const float*)d_in[14];
    const float* conv_w    = (const float*)d_in[15];
    const float* conv_b    = (const float*)d_in[16];
    const float* xproj_w   = (const float*)d_in[17];
    const float* dtproj_w  = (const float*)d_in[18];
    const float* dtproj_b  = (const float*)d_in[19];
    const float* A_log     = (const float*)d_in[20];
    const float* D_param   = (const float*)d_in[21];
    const float* out_proj_w= (const float*)d_in[22];
    const float* gate_w    = (const float*)d_in[23];
    const float* gate_b    = (const float*)d_in[24];
    const float* idn_g     = (const float*)d_in[25];
    const float* idn_b     = (const float*)d_in[26];
    const float* idbn_g    = (const float*)d_in[27];
    const float* idbn_b    = (const float*)d_in[28];
    float* out = (float*)d_out;

    __half *wh, *h, *h2, *xnh, *xm, *z, *xmc, *dbc, *del, *y, *mo, *gt;
    float *x1, *xf, *rm, *rs, *cm, *cs, *ps, *pq;
    cudaGetSymbolAddress((void**)&wh,  g_wh);
    cudaGetSymbolAddress((void**)&h,   g_h);
    cudaGetSymbolAddress((void**)&h2,  g_h2);
    cudaGetSymbolAddress((void**)&xnh, g_xnh);
    cudaGetSymbolAddress((void**)&xm,  g_xm);
    cudaGetSymbolAddress((void**)&z,   g_z);
    cudaGetSymbolAddress((void**)&xmc, g_xmc);
    cudaGetSymbolAddress((void**)&dbc, g_dbc);
    cudaGetSymbolAddress((void**)&del, g_del);
    cudaGetSymbolAddress((void**)&y,   g_y);
    cudaGetSymbolAddress((void**)&mo,  g_mo);
    cudaGetSymbolAddress((void**)&gt,  g_gt);
    cudaGetSymbolAddress((void**)&x1,  g_x1);
    cudaGetSymbolAddress((void**)&xf,  g_xf);
    cudaGetSymbolAddress((void**)&rm,  g_rm);
    cudaGetSymbolAddress((void**)&rs,  g_rs);
    cudaGetSymbolAddress((void**)&cm,  g_cm);
    cudaGetSymbolAddress((void**)&cs,  g_cs);
    cudaGetSymbolAddress((void**)&ps,  g_ps);
    cudaGetSymbolAddress((void**)&pq,  g_pq);

    cudaFuncSetAttribute(tgemm, cudaFuncAttributeMaxDynamicSharedMemorySize, TG_SMEMB);

    const long tD = (long)ML * DM;
    const long tH = (long)ML * NHID;
    const long tI = (long)ML * DI;

    // 0. convert all weights in one launch; x -> half
    wconv<<<(WH_TOT / 2 + 255) / 256, 256>>>(sq_w, ex_w, in_proj_w, xproj_w,
                                             dtproj_w, out_proj_w, gate_w, wh);
    f2h2<<<(int)((tD / 2 + 255) / 256), 256>>>(x, xnh, tD);

    // 1. squeeze proj + BN + silu
    tgemm<<<tg_grid(NHID), 256, TG_SMEMB>>>(xnh, DM, wh + OFF_SQ, DM, nullptr,
                                            h, NHID, nullptr, 0, 1 << 30, ML, NHID, DM, 0);
    bn_part<<<dim3(NHID / 32, BNCH), dim3(32, 32)>>>(h, ML, NHID, ps, pq);
    bn_final<<<1, NHID>>>(ps, pq, ML, NHID, cm, cs);
    bn_apply_hh<<<(tH + 255) / 256, 256>>>(h, h, cm, cs, sq_bn_g, sq_bn_b, tH, NHID);

    // 2. depthwise conv5 + BN + silu
    dwconv5_h<<<(tH + 255) / 256, 256>>>(h, dw_w, h2);
    bn_part<<<dim3(NHID / 32, BNCH), dim3(32, 32)>>>(h2, ML, NHID, ps, pq);
    bn_final<<<1, NHID>>>(ps, pq, ML, NHID, cm, cs);
    bn_apply_hh<<<(tH + 255) / 256, 256>>>(h2, h2, cm, cs, dw_bn_g, dw_bn_b, tH, NHID);

    // 3. expand proj -> mo; BN stats
    tgemm<<<tg_grid(DM), 256, TG_SMEMB>>>(h2, NHID, wh + OFF_EX, NHID, nullptr,
                                          mo, DM, nullptr, 0, 1 << 30, ML, DM, NHID, 0);
    bn_part<<<dim3(DM / 32, BNCH), dim3(32, 32)>>>(mo, ML, DM, ps, pq);
    bn_final<<<3, 256>>>(ps, pq, ML, DM, cm, cs);

    // 4/5. fused BN+resid -> x1, LN -> xn (+stats); feat_attr
    bnx1_ln<<<ML, 256>>>(mo, x, cm, cs, ex_bn_g, ex_bn_b, mnorm_g, mnorm_b, x1, xnh, rm, rs);
    feat_attr_k<<<dim3(DM / 32, BSZ), dim3(32, 8)>>>(x1, rm, rs, attr_g, attr_b, out);

    // 6. in_proj -> xm | z
    tgemm<<<tg_grid(2 * DI), 256, TG_SMEMB>>>(xnh, DM, wh + OFF_INP, DM, nullptr,
                                              xm, DI, z, DI, DI, ML, 2 * DI, DM, 0);

    // 7. causal conv4 + bias + silu -> xmc
    cconv4_h<<<(tI + 255) / 256, 256>>>(xm, conv_w, conv_b, xmc);

    // 8. xproj -> dbc (dt | B | C)
    tgemm<<<tg_grid(DXP), 256, TG_SMEMB>>>(xmc, DI, wh + OFF_XP, DI, nullptr,
                                           dbc, DXP, nullptr, 0, 1 << 30, ML, DXP, DI, 0);

    // 9. dtproj + bias + softplus -> delta
    tgemm<<<tg_grid(DI), 256, TG_SMEMB>>>(dbc, DXP, wh + OFF_DT, DTR, dtproj_b,
                                          del, DI, nullptr, 0, 1 << 30, ML, DI, DTR, 2);

    // 10/11. selective scan -> y
    scan_k<<<dim3(DI / 128, BSZ), 128>>>(xmc, del, dbc, z, A_log, D_param, y);

    // 12. out_proj -> mamba_out
    tgemm<<<tg_grid(DM), 256, TG_SMEMB>>>(y, DI, wh + OFF_OP, DI, nullptr,
                                          mo, DM, nullptr, 0, 1 << 30, ML, DM, DI, 0);

    // 13. gate
    tgemm<<<tg_grid(DM), 256, TG_SMEMB>>>(xnh, DM, wh + OFF_GW, DM, gate_b,
                                          gt, DM, nullptr, 0, 1 << 30, ML, DM, DM, 3);

    // 14/15. fused x_final + LN stats; feat_id
    xfinal_ln<<<ML, 256>>>(x1, mo, gt, x, xf, rm, rs);
    feat_id_k<<<dim3(DM / 32, BSZ), dim3(32, 8)>>>(xf, rm, rs, idn_g, idn_b, out + (long)BSZ * DM);

    // 16. BN over batch -> feat_id_bn
    idbn_k<<<DM / 256, 256>>>(out + (long)BSZ * DM, idbn_g, idbn_b, out + 2L * BSZ * DM);
}

// round 11
// speedup vs baseline: 1.5045x; 1.5045x over previous
#include <cuda_runtime.h>
#include <cuda_fp16.h>
#include <math.h>
#include <stdint.h>

#define BSZ   32
#define LQ    512
#define DM    768
#define NHID  192
#define KC    5
#define DI    1536
#define DS    16
#define DTR   48
#define DXP   (DTR+2*DS)      // 112
#define DCONV 4
#define ML    (BSZ*LQ)        // 16384 rows
#define EPSV  1e-5f
#define BNCH  32              // BN stats row-chunks

// fp16-mma GEMM tiling: CTA 128x128, K-chunk 32 halfs, 8 warps 4x2
#define TGK     32
#define PITCHW  20
#define TILEW   (128*PITCHW)
#define TG_SMEMB (4*TILEW*4)            // 40960 bytes

// weight scratch offsets (halfs)
#define OFF_SQ  0
#define OFF_EX  147456
#define OFF_INP 294912
#define OFF_XP  2654208
#define OFF_DT  2826240
#define OFF_OP  2899968
#define OFF_GW  4079616
#define WH_TOT  4669440

// ---------------- scratch buffers ----------------
__device__ __half g_wh [WH_TOT];
__device__ __half g_h  [ML*NHID];
__device__ __half g_h2 [ML*NHID];
__device__ __half g_xnh[ML*DM];
__device__ __half g_xm [(size_t)ML*DI];
__device__ __half g_z  [(size_t)ML*DI];
__device__ __half g_xmc[(size_t)ML*DI];
__device__ __half g_dbc[ML*DXP];
__device__ __half g_del[(size_t)ML*DI];
__device__ __half g_y  [(size_t)ML*DI];
__device__ __half g_mo [ML*DM];
__device__ __half g_gt [ML*DM];
__device__ float  g_x1 [ML*DM];
__device__ float  g_xf [ML*DM];
__device__ float  g_rm [ML];
__device__ float  g_rs [ML];
__device__ float  g_cm [4096];
__device__ float  g_cs [4096];
__device__ float  g_ps [BNCH*1024];
__device__ float  g_pq [BNCH*1024];

// ===================== helpers =============================================
__device__ __forceinline__ void mma_f16(float* d, const uint32_t* a, const uint32_t* b) {
    asm volatile(
        "mma.sync.aligned.m16n8k16.row.col.f32.f16.f16.f32 "
        "{%0,%1,%2,%3}, {%4,%5,%6,%7}, {%8,%9}, {%0,%1,%2,%3};"
        : "+f"(d[0]), "+f"(d[1]), "+f"(d[2]), "+f"(d[3])
        : "r"(a[0]), "r"(a[1]), "r"(a[2]), "r"(a[3]), "r"(b[0]), "r"(b[1]));
}
__device__ __forceinline__ void ldsm_x4(uint32_t& r0, uint32_t& r1, uint32_t& r2,
                                        uint32_t& r3, uint32_t addr) {
    asm volatile("ldmatrix.sync.aligned.m8n8.x4.shared.b16 {%0,%1,%2,%3}, [%4];"
                 : "=r"(r0), "=r"(r1), "=r"(r2), "=r"(r3) : "r"(addr));
}
__device__ __forceinline__ float fsilu(float v)   { return __fdividef(v, 1.f + __expf(-v)); }
__device__ __forceinline__ float fsigm(float v)   { return __fdividef(1.f, 1.f + __expf(-v)); }

// ---------------- converts -------------------------------------------------
__global__ void f2h2(const float* __restrict__ src, __half* __restrict__ dst, long n)
{
    long i = ((long)blockIdx.x * blockDim.x + threadIdx.x) * 2;
    if (i >= n) return;
    float2 v = *(const float2*)(src + i);
    *(__half2*)(dst + i) = __floats2half2_rn(v.x, v.y);
}
__global__ void wconv(const float* __restrict__ s0, const float* __restrict__ s1,
                      const float* __restrict__ s2, const float* __restrict__ s3,
                      const float* __restrict__ s4, const float* __restrict__ s5,
                      const float* __restrict__ s6, __half* __restrict__ dst)
{
    long i = ((long)blockIdx.x * blockDim.x + threadIdx.x) * 2;
    if (i >= WH_TOT) return;
    const float* src; long off;
    if      (i < OFF_EX)  { src = s0; off = i - OFF_SQ;  }
    else if (i < OFF_INP) { src = s1; off = i - OFF_EX;  }
    else if (i < OFF_XP)  { src = s2; off = i - OFF_INP; }
    else if (i < OFF_DT)  { src = s3; off = i - OFF_XP;  }
    else if (i < OFF_OP)  { src = s4; off = i - OFF_DT;  }
    else if (i < OFF_GW)  { src = s5; off = i - OFF_OP;  }
    else                  { src = s6; off = i - OFF_GW;  }
    float2 v = *(const float2*)(src + off);
    *(__half2*)(dst + i) = __floats2half2_rn(v.x, v.y);
}

// ===================== fp16 tensor GEMM (ldmatrix) =========================
__global__ void __launch_bounds__(256, 2)
tgemm(const __half* __restrict__ A, int lda,
      const __half* __restrict__ W, int ldw,
      const float* __restrict__ bias,
      __half* __restrict__ C, int ldc,
      __half* __restrict__ C2, int ldc2, int splitN,
      int M, int N, int K, int act)
{
    extern __shared__ uint32_t smem[];
    const int tid = threadIdx.x;
    const int wid = tid >> 5, lane = tid & 31;
    const int g = lane >> 2, t = lane & 3;
    const int wm = wid & 3, wn = wid >> 2;
    const int row0 = blockIdx.y * 128, col0 = blockIdx.x * 128;
    const uint32_t smem_b = (uint32_t)__cvta_generic_to_shared(smem);

    // ldmatrix lane->address components (in 4B words)
    const int a_row = lane & 15;
    const int a_kw  = (lane >> 4) * 4;
    const int b_row = (lane & 7) + ((lane >> 4) << 3);
    const int b_kw  = ((lane >> 3) & 1) * 4;

    float acc[2][8][4];
#pragma unroll
    for (int mt = 0; mt < 2; mt++)
#pragma unroll
        for (int nt = 0; nt < 8; nt++)
#pragma unroll
            for (int j = 0; j < 4; j++) acc[mt][nt][j] = 0.f;

    const int nch = (K + TGK - 1) / TGK;

    uint4 pa[2], pb[2];
    auto ldg_chunk = [&](int ch) {
        const int k0 = ch * TGK;
#pragma unroll
        for (int i = 0; i < 2; i++) {
            int e = tid + i * 256;
            int r = e >> 2, q = e & 3;
            int gk = k0 + q * 8;
            pa[i] = make_uint4(0, 0, 0, 0);
            pb[i] = make_uint4(0, 0, 0, 0);
            if (gk < K) {
                pa[i] = *(const uint4*)(A + (long)(row0 + r) * lda + gk);
                int n = col0 + r;
                if (n < N) pb[i] = *(const uint4*)(W + (long)n * ldw + gk);
            }
        }
    };
    auto sts_chunk = [&](int buf) {
        uint32_t* As = smem + buf * 2 * TILEW;
        uint32_t* Bs = As + TILEW;
#pragma unroll
        for (int i = 0; i < 2; i++) {
            int e = tid + i * 256;
            int r = e >> 2, q = e & 3;
            int o = r * PITCHW + q * 4;
            *(uint4*)(As + o) = pa[i];
            *(uint4*)(Bs + o) = pb[i];
        }
    };
    auto compute_chunk = [&](int buf) {
        const uint32_t Ab = smem_b + (uint32_t)(buf * 2 * TILEW) * 4;
        const uint32_t Bb = Ab + TILEW * 4;
#pragma unroll
        for (int ks = 0; ks < 2; ks++) {
            const int kw = ks * 8;
            uint32_t af[2][4], bf[8][2];
#pragma unroll
            for (int mt = 0; mt < 2; mt++) {
                uint32_t addr = Ab + (uint32_t)(((wm * 32 + mt * 16 + a_row) * PITCHW
                                                + kw + a_kw) * 4);
                ldsm_x4(af[mt][0], af[mt][1], af[mt][2], af[mt][3], addr);
            }
#pragma unroll
            for (int j = 0; j < 4; j++) {
                uint32_t addr = Bb + (uint32_t)(((wn * 64 + j * 16 + b_row) * PITCHW
                                                + kw + b_kw) * 4);
                ldsm_x4(bf[2 * j][0], bf[2 * j][1], bf[2 * j + 1][0], bf[2 * j + 1][1], addr);
            }
#pragma unroll
            for (int mt = 0; mt < 2; mt++)
#pragma unroll
                for (int nt = 0; nt < 8; nt++)
                    mma_f16(acc[mt][nt], af[mt], bf[nt]);
        }
    };

    ldg_chunk(0);
    sts_chunk(0);
    __syncthreads();
    for (int ch = 1; ch < nch; ch++) {
        ldg_chunk(ch);
        compute_chunk((ch - 1) & 1);
        sts_chunk(ch & 1);
        __syncthreads();
    }
    compute_chunk((nch - 1) & 1);

    __half* Cp = C; int cof = col0, ldco = ldc;
    if (C2 && col0 >= splitN) { Cp = C2; cof = col0 - splitN; ldco = ldc2; }
#pragma unroll
    for (int mt = 0; mt < 2; mt++) {
        int r0 = row0 + wm * 32 + mt * 16 + g;
#pragma unroll
        for (int nt = 0; nt < 8; nt++) {
            int c0 = cof + wn * 64 + nt * 8 + t * 2;
            int cg = col0 + wn * 64 + nt * 8 + t * 2;
            if (cg >= N) continue;
#pragma unroll
            for (int half_ = 0; half_ < 2; half_++) {
                int r = r0 + half_ * 8;
                float v0 = acc[mt][nt][half_ * 2 + 0];
                float v1 = acc[mt][nt][half_ * 2 + 1];
                if (bias) { v0 += bias[cg]; v1 += bias[cg + 1]; }
                if (act == 2) {
                    v0 = (v0 > 20.f) ? v0 : log1pf(__expf(v0));
                    v1 = (v1 > 20.f) ? v1 : log1pf(__expf(v1));
                } else if (act == 3) {
                    v0 = fsigm(v0);
                    v1 = fsigm(v1);
                }
                *(__half2*)(Cp + (long)r * ldco + c0) = __floats2half2_rn(v0, v1);
            }
        }
    }
}

// ===================== two-phase BN stats ==================================
__global__ void bn_part(const __half* __restrict__ src, int M, int N,
                        float* __restrict__ ps, float* __restrict__ pq)
{
    int c = blockIdx.x * 32 + threadIdx.x;
    int ch = blockIdx.y;
    int rows = M / BNCH;
    int r0 = ch * rows;
    float s = 0.f, sq = 0.f;
    if (c < N) {
        for (int r = r0 + threadIdx.y; r < r0 + rows; r += blockDim.y) {
            float v = __half2float(src[(long)r * N + c]);
            s += v; sq += v * v;
        }
    }
    __shared__ float sh[32][33], sh2[32][33];
    sh[threadIdx.y][threadIdx.x] = s;
    sh2[threadIdx.y][threadIdx.x] = sq;
    __syncthreads();
    if (threadIdx.y == 0 && c < N) {
#pragma unroll
        for (int i = 1; i < 32; i++) { s += sh[i][threadIdx.x]; sq += sh2[i][threadIdx.x]; }
        ps[ch * N + c] = s;
        pq[ch * N + c] = sq;
    }
}
__global__ void bn_final(const float* __restrict__ ps, const float* __restrict__ pq,
                         int M, int N, float* __restrict__ mean, float* __restrict__ rstd)
{
    int c = blockIdx.x * blockDim.x + threadIdx.x;
    if (c >= N) return;
    float s = 0.f, sq = 0.f;
#pragma unroll
    for (int ch = 0; ch < BNCH; ch++) { s += ps[ch * N + c]; sq += pq[ch * N + c]; }
    float m = s / (float)M;
    mean[c] = m;
    rstd[c] = rsqrtf(fmaxf(sq / (float)M - m * m, 0.f) + EPSV);
}

__global__ void bn_apply_hh(const __half* __restrict__ src, __half* __restrict__ dst,
                            const float* __restrict__ mean, const float* __restrict__ rstd,
                            const float* __restrict__ g, const float* __restrict__ b,
                            long total, int N)
{
    long i = (long)blockIdx.x * blockDim.x + threadIdx.x;
    if (i >= total) return;
    int c = (int)(i % N);
    float v = (__half2float(src[i]) - mean[c]) * rstd[c] * g[c] + b[c];
    dst[i] = __float2half_rn(fsilu(v));
}

__global__ void dwconv5_h(const __half* __restrict__ src, const float* __restrict__ w,
                          __half* __restrict__ dst)
{
    long i = (long)blockIdx.x * blockDim.x + threadIdx.x;
    if (i >= (long)ML * NHID) return;
    int c = (int)(i % NHID);
    long bl = i / NHID;
    int l = (int)(bl % LQ);
    long b = bl / LQ;
    float acc = 0.f;
#pragma unroll
    for (int k = 0; k < KC; k++) {
        int ll = l + k - 2;
        if (ll >= 0 && ll < LQ)
            acc += __half2float(src[(b * LQ + ll) * NHID + c]) * w[c * KC + k];
    }
    dst[i] = __float2half_rn(acc);
}

__global__ void cconv4_h(const __half* __restrict__ xm, const float* __restrict__ w,
                         const float* __restrict__ cb, __half* __restrict__ dst)
{
    long i = (long)blockIdx.x * blockDim.x + threadIdx.x;
    if (i >= (long)ML * DI) return;
    int c = (int)(i % DI);
    long bl = i / DI;
    int l = (int)(bl % LQ);
    long b = bl / LQ;
    float acc = cb[c];
#pragma unroll
    for (int k = 0; k < DCONV; k++) {
        int ll = l + k - (DCONV - 1);
        if (ll >= 0)
            acc += __half2float(xm[(b * LQ + ll) * (long)DI + c]) * w[c * DCONV + k];
    }
    dst[i] = __float2half_rn(fsilu(acc));
}

// fused BN(ex)+residual -> x1 ; LN stats ; LN apply -> xn (half)
__global__ void bnx1_ln(const __half* __restrict__ mo, const float* __restrict__ x,
                        const float* __restrict__ cm, const float* __restrict__ cs,
                        const float* __restrict__ exg, const float* __restrict__ exb,
                        const float* __restrict__ mg, const float* __restrict__ mb,
                        float* __restrict__ x1, __half* __restrict__ xn,
                        float* __restrict__ rm, float* __restrict__ rs)
{
    int r = blockIdx.x;
    long base = (long)r * DM;
    float v[3];
#pragma unroll
    for (int i = 0; i < 3; i++) {
        int c = threadIdx.x + i * 256;
        float bn = (__half2float(mo[base + c]) - cm[c]) * cs[c] * exg[c] + exb[c];
        v[i] = bn + x[base + c];
        x1[base + c] = v[i];
    }
    float s = v[0] + v[1] + v[2];
    float sq = v[0] * v[0] + v[1] * v[1] + v[2] * v[2];
    __shared__ float sh[256], sh2[256];
    sh[threadIdx.x] = s; sh2[threadIdx.x] = sq;
    __syncthreads();
    for (int st = 128; st > 0; st >>= 1) {
        if (threadIdx.x < st) { sh[threadIdx.x] += sh[threadIdx.x + st]; sh2[threadIdx.x] += sh2[threadIdx.x + st]; }
        __syncthreads();
    }
    float m = sh[0] / (float)DM;
    float rstd = rsqrtf(fmaxf(sh2[0] / (float)DM - m * m, 0.f) + EPSV);
    if (threadIdx.x == 0) { rm[r] = m; rs[r] = rstd; }
#pragma unroll
    for (int i = 0; i < 3; i++) {
        int c = threadIdx.x + i * 256;
        xn[base + c] = __float2half_rn((v[i] - m) * rstd * mg[c] + mb[c]);
    }
}

// fused x_final + LN stats
__global__ void xfinal_ln(const float* __restrict__ x1, const __half* __restrict__ mo,
                          const __half* __restrict__ gt, const float* __restrict__ x,
                          float* __restrict__ xf, float* __restrict__ rm,
                          float* __restrict__ rs)
{
    int r = blockIdx.x;
    long base = (long)r * DM;
    float v[3];
#pragma unroll
    for (int i = 0; i < 3; i++) {
        int c = threadIdx.x + i * 256;
        v[i] = x1[base + c] + __half2float(mo[base + c]) * __half2float(gt[base + c]) + x[base + c];
        xf[base + c] = v[i];
    }
    float s = v[0] + v[1] + v[2];
    float sq = v[0] * v[0] + v[1] * v[1] + v[2] * v[2];
    __shared__ float sh[256], sh2[256];
    sh[threadIdx.x] = s; sh2[threadIdx.x] = sq;
    __syncthreads();
    for (int st = 128; st > 0; st >>= 1) {
        if (threadIdx.x < st) { sh[threadIdx.x] += sh[threadIdx.x + st]; sh2[threadIdx.x] += sh2[threadIdx.x + st]; }
        __syncthreads();
    }
    if (threadIdx.x == 0) {
        float m = sh[0] / (float)DM;
        rm[r] = m;
        rs[r] = rsqrtf(fmaxf(sh2[0] / (float)DM - m * m, 0.f) + EPSV);
    }
}

__global__ void feat_attr_k(const float* __restrict__ x1, const float* __restrict__ rm,
                            const float* __restrict__ rs, const float* __restrict__ g,
                            const float* __restrict__ b, float* __restrict__ out)
{
    int d = blockIdx.x * 32 + threadIdx.x;
    int bb = blockIdx.y;
    float gd = g[d], bd = b[d];
    float best = -1e30f;
    for (int l = threadIdx.y; l < LQ; l += 8) {
        long row = (long)bb * LQ + l;
        float v = (x1[row * DM + d] - rm[row]) * rs[row] * gd + bd;
        best = fmaxf(best, v);
    }
    __shared__ float sh[8][33];
    sh[threadIdx.y][threadIdx.x] = best;
    __syncthreads();
    if (threadIdx.y == 0) {
#pragma unroll
        for (int i = 1; i < 8; i++) best = fmaxf(best, sh[i][threadIdx.x]);
        out[(long)bb * DM + d] = best;
    }
}

__global__ void feat_id_k(const float* __restrict__ xf, const float* __restrict__ rm,
                          const float* __restrict__ rs, const float* __restrict__ g,
                          const float* __restrict__ b, float* __restrict__ out)
{
    int d = blockIdx.x * 32 + threadIdx.x;
    int bb = blockIdx.y;
    float acc = 0.f;
    for (int l = threadIdx.y; l < LQ; l += 8) {
        long row = (long)bb * LQ + l;
        acc += (xf[row * DM + d] - rm[row]) * rs[row];
    }
    __shared__ float sh[8][33];
    sh[threadIdx.y][threadIdx.x] = acc;
    __syncthreads();
    if (threadIdx.y == 0) {
#pragma unroll
        for (int i = 1; i < 8; i++) acc += sh[i][threadIdx.x];
        out[(long)bb * DM + d] = (acc / (float)LQ) * g[d] + b[d];
    }
}

__global__ void idbn_k(const float* __restrict__ fid, const float* __restrict__ g,
                       const float* __restrict__ b, float* __restrict__ out)
{
    int d = blockIdx.x * blockDim.x + threadIdx.x;
    if (d >= DM) return;
    float s = 0.f;
    for (int bb = 0; bb < BSZ; bb++) s += fid[(long)bb * DM + d];
    float m = s / (float)BSZ;
    float vq = 0.f;
    for (int bb = 0; bb < BSZ; bb++) { float dv = fid[(long)bb * DM + d] - m; vq += dv * dv; }
    float rst = rsqrtf(vq / (float)BSZ + EPSV);
    for (int bb = 0; bb < BSZ; bb++)
        out[(long)bb * DM + d] = (fid[(long)bb * DM + d] - m) * rst * g[d] + b[d];
}

// ---------------- selective scan (half inputs, prefetched) ----------------
__global__ void __launch_bounds__(128)
scan_k(const __half* __restrict__ xmc, const __half* __restrict__ del,
       const __half* __restrict__ dbc, const __half* __restrict__ z,
       const float* __restrict__ A_log, const float* __restrict__ Dp,
       __half* __restrict__ y)
{
    int b = blockIdx.y;
    int d = blockIdx.x * 128 + threadIdx.x;
    float A[DS], h[DS];
    bool fast = true;
#pragma unroll
    for (int s = 0; s < DS; s++) {
        A[s] = -expf(A_log[(long)d * DS + s]);
        h[s] = 0.f;
        fast = fast && (fabsf(A[s] + (float)(s + 1)) < 1e-4f * (float)(s + 1));
    }
    float Dpv = Dp[d];
    const long rb0 = (long)b * LQ;
    const __half* dbcb = dbc + rb0 * DXP + DTR;

    float dv = __half2float(del[rb0 * DI + d]);
    float uv = __half2float(xmc[rb0 * DI + d]);
    float zv = __half2float(z[rb0 * DI + d]);
    uint4 bc[4];
#pragma unroll
    for (int i = 0; i < 4; i++) bc[i] = *(const uint4*)(dbcb + i * 8);

    for (int l = 0; l < LQ; l++) {
        float dvn = 0.f, uvn = 0.f, zvn = 0.f;
        uint4 bcn[4] = {};
        if (l + 1 < LQ) {
            long rb = rb0 + l + 1;
            dvn = __half2float(del[rb * DI + d]);
            uvn = __half2float(xmc[rb * DI + d]);
            zvn = __half2float(z[rb * DI + d]);
            const __half* p = dbcb + (long)(l + 1) * DXP;
#pragma unroll
            for (int i = 0; i < 4; i++) bcn[i] = *(const uint4*)(p + i * 8);
        }

        float Bv[DS], Cv[DS];
#pragma unroll
        for (int i = 0; i < 2; i++) {
            const __half2* hb = (const __half2*)&bc[i];
#pragma unroll
            for (int j = 0; j < 4; j++) {
                float2 f = __half22float2(hb[j]);
                Bv[i * 8 + j * 2] = f.x; Bv[i * 8 + j * 2 + 1] = f.y;
            }
            const __half2* hc = (const __half2*)&bc[i + 2];
#pragma unroll
            for (int j = 0; j < 4; j++) {
                float2 f = __half22float2(hc[j]);
                Cv[i * 8 + j * 2] = f.x; Cv[i * 8 + j * 2 + 1] = f.y;
            }
        }

        float du = dv * uv;
        float yv = 0.f;
        if (fast) {
            float p = __expf(-dv), e = 1.f;
#pragma unroll
            for (int s = 0; s < DS; s++) {
                e *= p;
                h[s] = h[s] * e + du * Bv[s];
                yv += h[s] * Cv[s];
            }
        } else {
#pragma unroll
            for (int s = 0; s < DS; s++) {
                float e = __expf(dv * A[s]);
                h[s] = h[s] * e + du * Bv[s];
                yv += h[s] * Cv[s];
            }
        }
        yv += uv * Dpv;
        y[(rb0 + l) * DI + d] = __float2half_rn(yv * fsilu(zv));

        dv = dvn; uv = uvn; zv = zvn;
#pragma unroll
        for (int i = 0; i < 4; i++) bc[i] = bcn[i];
    }
}

// ======================== host launcher ====================================
static inline dim3 tg_grid(int N) { return dim3((N + 127) / 128, ML / 128); }

extern "C" void kernel_launch(void* const* d_in, const int* in_sizes, int n_in,
                              void* d_out, int out_size)
{
    (void)in_sizes; (void)n_in; (void)out_size;
    const float* x         = (const float*)d_in[0];
    const float* sq_w      = (const float*)d_in[1];
    const float* sq_bn_g   = (const float*)d_in[2];
    const float* sq_bn_b   = (const float*)d_in[3];
    const float* dw_w      = (const float*)d_in[4];
    const float* dw_bn_g   = (const float*)d_in[5];
    const float* dw_bn_b   = (const float*)d_in[6];
    const float* ex_w      = (const float*)d_in[7];
    const float* ex_bn_g   = (const float*)d_in[8];
    const float* ex_bn_b   = (const float*)d_in[9];
    const float* attr_g    = (const float*)d_in[10];
    const float* attr_b    = (const float*)d_in[11];
    const float* mnorm_g   = (const float*)d_in[12];
    const float* mnorm_b   = (const float*)d_in[13];
    const float* in_proj_w = (const float*)d_in[14];
    const float* conv_w    = (const float*)d_in[15];
    const float* conv_b    = (const float*)d_in[16];
    const float* xproj_w   = (const float*)d_in[17];
    const float* dtproj_w  = (const float*)d_in[18];
    const float* dtproj_b  = (const float*)d_in[19];
    const float* A_log     = (const float*)d_in[20];
    const float* D_param   = (const float*)d_in[21];
    const float* out_proj_w= (const float*)d_in[22];
    const float* gate_w    = (const float*)d_in[23];
    const float* gate_b    = (const float*)d_in[24];
    const float* idn_g     = (const float*)d_in[25];
    const float* idn_b     = (const float*)d_in[26];
    const float* idbn_g    = (const float*)d_in[27];
    const float* idbn_b    = (const float*)d_in[28];
    float* out = (float*)d_out;

    __half *wh, *h, *h2, *xnh, *xm, *z, *xmc, *dbc, *del, *y, *mo, *gt;
    float *x1, *xf, *rm, *rs, *cm, *cs, *ps, *pq;
    cudaGetSymbolAddress((void**)&wh,  g_wh);
    cudaGetSymbolAddress((void**)&h,   g_h);
    cudaGetSymbolAddress((void**)&h2,  g_h2);
    cudaGetSymbolAddress((void**)&xnh, g_xnh);
    cudaGetSymbolAddress((void**)&xm,  g_xm);
    cudaGetSymbolAddress((void**)&z,   g_z);
    cudaGetSymbolAddress((void**)&xmc, g_xmc);
    cudaGetSymbolAddress((void**)&dbc, g_dbc);
    cudaGetSymbolAddress((void**)&del, g_del);
    cudaGetSymbolAddress((void**)&y,   g_y);
    cudaGetSymbolAddress((void**)&mo,  g_mo);
    cudaGetSymbolAddress((void**)&gt,  g_gt);
    cudaGetSymbolAddress((void**)&x1,  g_x1);
    cudaGetSymbolAddress((void**)&xf,  g_xf);
    cudaGetSymbolAddress((void**)&rm,  g_rm);
    cudaGetSymbolAddress((void**)&rs,  g_rs);
    cudaGetSymbolAddress((void**)&cm,  g_cm);
    cudaGetSymbolAddress((void**)&cs,  g_cs);
    cudaGetSymbolAddress((void**)&ps,  g_ps);
    cudaGetSymbolAddress((void**)&pq,  g_pq);

    cudaFuncSetAttribute(tgemm, cudaFuncAttributeMaxDynamicSharedMemorySize, TG_SMEMB);

    const long tD = (long)ML * DM;
    const long tH = (long)ML * NHID;
    const long tI = (long)ML * DI;

    // 0. convert all weights in one launch; x -> half
    wconv<<<(WH_TOT / 2 + 255) / 256, 256>>>(sq_w, ex_w, in_proj_w, xproj_w,
                                             dtproj_w, out_proj_w, gate_w, wh);
    f2h2<<<(int)((tD / 2 + 255) / 256), 256>>>(x, xnh, tD);

    // 1. squeeze proj + BN + silu
    tgemm<<<tg_grid(NHID), 256, TG_SMEMB>>>(xnh, DM, wh + OFF_SQ, DM, nullptr,
                                            h, NHID, nullptr, 0, 1 << 30, ML, NHID, DM, 0);
    bn_part<<<dim3(NHID / 32, BNCH), dim3(32, 32)>>>(h, ML, NHID, ps, pq);
    bn_final<<<1, NHID>>>(ps, pq, ML, NHID, cm, cs);
    bn_apply_hh<<<(tH + 255) / 256, 256>>>(h, h, cm, cs, sq_bn_g, sq_bn_b, tH, NHID);

    // 2. depthwise conv5 + BN + silu
    dwconv5_h<<<(tH + 255) / 256, 256>>>(h, dw_w, h2);
    bn_part<<<dim3(NHID / 32, BNCH), dim3(32, 32)>>>(h2, ML, NHID, ps, pq);
    bn_final<<<1, NHID>>>(ps, pq, ML, NHID, cm, cs);
    bn_apply_hh<<<(tH + 255) / 256, 256>>>(h2, h2, cm, cs, dw_bn_g, dw_bn_b, tH, NHID);

    // 3. expand proj -> mo; BN stats
    tgemm<<<tg_grid(DM), 256, TG_SMEMB>>>(h2, NHID, wh + OFF_EX, NHID, nullptr,
                                          mo, DM, nullptr, 0, 1 << 30, ML, DM, NHID, 0);
    bn_part<<<dim3(DM / 32, BNCH), dim3(32, 32)>>>(mo, ML, DM, ps, pq);
    bn_final<<<3, 256>>>(ps, pq, ML, DM, cm, cs);

    // 4/5. fused BN+resid -> x1, LN -> xn (+stats); feat_attr
    bnx1_ln<<<ML, 256>>>(mo, x, cm, cs, ex_bn_g, ex_bn_b, mnorm_g, mnorm_b, x1, xnh, rm, rs);
    feat_attr_k<<<dim3(DM / 32, BSZ), dim3(32, 8)>>>(x1, rm, rs, attr_g, attr_b, out);

    // 6. in_proj -> xm | z
    tgemm<<<tg_grid(2 * DI), 256, TG_SMEMB>>>(xnh, DM, wh + OFF_INP, DM, nullptr,
                                              xm, DI, z, DI, DI, ML, 2 * DI, DM, 0);

    // 7. causal conv4 + bias + silu -> xmc
    cconv4_h<<<(tI + 255) / 256, 256>>>(xm, conv_w, conv_b, xmc);

    // 8. xproj -> dbc (dt | B | C)
    tgemm<<<tg_grid(DXP), 256, TG_SMEMB>>>(xmc, DI, wh + OFF_XP, DI, nullptr,
                                           dbc, DXP, nullptr, 0, 1 << 30, ML, DXP, DI, 0);

    // 9. dtproj + bias + softplus -> delta
    tgemm<<<tg_grid(DI), 256, TG_SMEMB>>>(dbc, DXP, wh + OFF_DT, DTR, dtproj_b,
                                          del, DI, nullptr, 0, 1 << 30, ML, DI, DTR, 2);

    // 10/11. selective scan -> y
    scan_k<<<dim3(DI / 128, BSZ), 128>>>(xmc, del, dbc, z, A_log, D_param, y);

    // 12. out_proj -> mamba_out
    tgemm<<<tg_grid(DM), 256, TG_SMEMB>>>(y, DI, wh + OFF_OP, DI, nullptr,
                                          mo, DM, nullptr, 0, 1 << 30, ML, DM, DI, 0);

    // 13. gate
    tgemm<<<tg_grid(DM), 256, TG_SMEMB>>>(xnh, DM, wh + OFF_GW, DM, gate_b,
                                          gt, DM, nullptr, 0, 1 << 30, ML, DM, DM, 3);

    // 14/15. fused x_final + LN stats; feat_id
    xfinal_ln<<<ML, 256>>>(x1, mo, gt, x, xf, rm, rs);
    feat_id_k<<<dim3(DM / 32, BSZ), dim3(32, 8)>>>(xf, rm, rs, idn_g, idn_b, out + (long)BSZ * DM);

    // 16. BN over batch -> feat_id_bn
    idbn_k<<<DM / 256, 256>>>(out + (long)BSZ * DM, idbn_g, idbn_b, out + 2L * BSZ * DM);
}